// round 4
// baseline (speedup 1.0000x reference)
#include <cuda_runtime.h>
#include <cuda_bf16.h>

// Problem constants (fixed by the reference): B=16, H=512, W=512 -> out 2H x 2W
#define BB 16
#define HI 512
#define WI 512
#define HO 1024
#define WO 1024

// Fused: bilinear 2x upsample of mask (half-pixel centers, edge-clamped ==
// JAX renormalized triangle weights), blend fused = xm*xl + ym*yl per channel,
// 3x3 channel-mix (1x1 conv) + bias + relu. Emits (out, x_mask, y_mask).
//
// R3: each thread handles the same x-quad in TWO output rows (2k, 2k+1),
// which share mask input row k. Doubles per-thread MLP (12 float4 loads,
// 10 float4 stores in flight) and cuts mask scalar loads 32->24/thread.
// Streaming cache hints (__ldcs/__stcs) keep L2 for the reused mask plane.
__global__ __launch_bounds__(256)
void fused_upsample_mix_kernel(const float* __restrict__ mask,
                               const float* __restrict__ xl,
                               const float* __restrict__ yl,
                               const float* __restrict__ cw,
                               const float* __restrict__ cb,
                               float* __restrict__ out)
{
    const int xq = threadIdx.x;        // 0..255, covers x0 = 4*xq
    const int k  = blockIdx.y;         // input mask row; outputs rows 2k, 2k+1
    const int b  = blockIdx.z;         // 0..B-1

    // Vertical source rows (clamped):
    //  out row 2k   : 0.25*m[k-1] + 0.75*m[k]
    //  out row 2k+1 : 0.75*m[k]   + 0.25*m[k+1]
    const int km1 = (k > 0) ? k - 1 : 0;
    const int kp1 = (k + 1 < HI) ? k + 1 : HI - 1;

    // Horizontal: output x in {4q..4q+3} need input cols t-1, t, t+1, t+2,
    // t = 2q (clamped).
    const int t   = xq * 2;
    const int cm1 = (t > 0) ? t - 1 : 0;
    const int c2  = (t + 2 < WI) ? t + 2 : WI - 1;

    // Upsampled mask: [channel][row 0/1][4 x-pixels]
    float m4[2][2][4];
#pragma unroll
    for (int ch = 0; ch < 2; ch++) {
        const float* pm = mask + (((size_t)b * 2 + ch) * HI + km1) * WI;
        const float* p0 = mask + (((size_t)b * 2 + ch) * HI + k)   * WI;
        const float* pp = mask + (((size_t)b * 2 + ch) * HI + kp1) * WI;
        float vm[4], v0[4], vp[4];
        vm[0] = __ldg(pm + cm1); vm[1] = __ldg(pm + t); vm[2] = __ldg(pm + t + 1); vm[3] = __ldg(pm + c2);
        v0[0] = __ldg(p0 + cm1); v0[1] = __ldg(p0 + t); v0[2] = __ldg(p0 + t + 1); v0[3] = __ldg(p0 + c2);
        vp[0] = __ldg(pp + cm1); vp[1] = __ldg(pp + t); vp[2] = __ldg(pp + t + 1); vp[3] = __ldg(pp + c2);
        // Vertical lerp first (JAX separable order), per needed input col.
        float a0[4], a1[4];
#pragma unroll
        for (int j = 0; j < 4; j++) {
            a0[j] = fmaf(0.25f, vm[j], 0.75f * v0[j]);  // for out row 2k
            a1[j] = fmaf(0.75f, v0[j], 0.25f * vp[j]);  // for out row 2k+1
        }
#pragma unroll
        for (int r = 0; r < 2; r++) {
            const float* a = r ? a1 : a0;
            m4[ch][r][0] = fmaf(0.25f, a[0], 0.75f * a[1]);  // x = 4q   (even)
            m4[ch][r][1] = fmaf(0.75f, a[1], 0.25f * a[2]);  // x = 4q+1 (odd)
            m4[ch][r][2] = fmaf(0.25f, a[1], 0.75f * a[2]);  // x = 4q+2 (even)
            m4[ch][r][3] = fmaf(0.75f, a[2], 0.25f * a[3]);  // x = 4q+3 (odd)
        }
    }

    // 3x3 channel-mix weights + bias (broadcast, L1-resident).
    const float w00 = __ldg(cw + 0), w01 = __ldg(cw + 1), w02 = __ldg(cw + 2);
    const float w10 = __ldg(cw + 3), w11 = __ldg(cw + 4), w12 = __ldg(cw + 5);
    const float w20 = __ldg(cw + 6), w21 = __ldg(cw + 7), w22 = __ldg(cw + 8);
    const float bs0 = __ldg(cb + 0), bs1 = __ldg(cb + 1), bs2 = __ldg(cb + 2);

    const size_t planeO = (size_t)HO * WO;
    const size_t x0     = (size_t)xq * 4;
    const int    y0     = k * 2;

    // Streaming loads for both rows up-front (maximize loads in flight).
    float4 xlv[2][3], ylv[2][3];
#pragma unroll
    for (int r = 0; r < 2; r++) {
        const size_t rowbase = (size_t)b * 3 * planeO + (size_t)(y0 + r) * WO + x0;
#pragma unroll
        for (int c = 0; c < 3; c++) {
            xlv[r][c] = __ldcs((const float4*)(xl + rowbase + (size_t)c * planeO));
            ylv[r][c] = __ldcs((const float4*)(yl + rowbase + (size_t)c * planeO));
        }
    }

#pragma unroll
    for (int r = 0; r < 2; r++) {
        float4 o0, o1, o2, xmv, ymv;
        float* o0p = (float*)&o0;  float* o1p = (float*)&o1;  float* o2p = (float*)&o2;
        float* xmp = (float*)&xmv; float* ymp = (float*)&ymv;
#pragma unroll
        for (int j = 0; j < 4; j++) {
            const float xm = m4[0][r][j];
            const float ym = m4[1][r][j];
            const float f0 = fmaf(xm, ((const float*)&xlv[r][0])[j], ym * ((const float*)&ylv[r][0])[j]);
            const float f1 = fmaf(xm, ((const float*)&xlv[r][1])[j], ym * ((const float*)&ylv[r][1])[j]);
            const float f2 = fmaf(xm, ((const float*)&xlv[r][2])[j], ym * ((const float*)&ylv[r][2])[j]);
            o0p[j] = fmaxf(fmaf(w00, f0, fmaf(w01, f1, fmaf(w02, f2, bs0))), 0.0f);
            o1p[j] = fmaxf(fmaf(w10, f0, fmaf(w11, f1, fmaf(w12, f2, bs1))), 0.0f);
            o2p[j] = fmaxf(fmaf(w20, f0, fmaf(w21, f1, fmaf(w22, f2, bs2))), 0.0f);
            xmp[j] = xm;
            ymp[j] = ym;
        }

        const size_t rowbase  = (size_t)b * 3 * planeO + (size_t)(y0 + r) * WO + x0;
        __stcs((float4*)(out + rowbase),              o0);
        __stcs((float4*)(out + rowbase + planeO),     o1);
        __stcs((float4*)(out + rowbase + 2 * planeO), o2);

        const size_t maskbase = (size_t)BB * 3 * planeO
                              + (size_t)b * planeO + (size_t)(y0 + r) * WO + x0;
        __stcs((float4*)(out + maskbase),                       xmv);
        __stcs((float4*)(out + maskbase + (size_t)BB * planeO), ymv);
    }
}

extern "C" void kernel_launch(void* const* d_in, const int* in_sizes, int n_in,
                              void* d_out, int out_size) {
    const float* mask = (const float*)d_in[0];  // (16,2,512,512)
    const float* xl   = (const float*)d_in[1];  // (16,3,1024,1024)
    const float* yl   = (const float*)d_in[2];  // (16,3,1024,1024)
    const float* cw   = (const float*)d_in[3];  // (3,3)
    const float* cb   = (const float*)d_in[4];  // (3,)
    float* out = (float*)d_out;

    dim3 grid(1, HO / 2, BB);   // block = 2 output rows; 256 threads cover WO/4
    dim3 block(256);
    fused_upsample_mix_kernel<<<grid, block>>>(mask, xl, yl, cw, cb, out);
}